// round 7
// baseline (speedup 1.0000x reference)
#include <cuda_runtime.h>
#include <cuda_fp16.h>
#include <math.h>

#define HF 200
#define WF 200
#define CH 256
#define HO 7
#define WO 7
#define SUBS 2
#define HS (HO * SUBS)   // 14
#define WS (WO * SUBS)   // 14

#define ROW_BYTES (WF * CH * 2)   // 102400
#define COL_BYTES (CH * 2)        // 512
#define SPITCH 264                // halves per staged position (256 + 8 pad)

// Channels-last fp16 scratch copy: g_featTh[(y*WF + x)*CH + c]  (20.5 MB)
__device__ __align__(16) __half g_featTh[HF * WF * CH];

static __device__ __forceinline__ __half2 u2h2(unsigned u) {
    return *reinterpret_cast<__half2*>(&u);
}
static __device__ __forceinline__ __half2 lerp2(__half2 ul, __half2 ur,
                                                __half2 dl, __half2 dr,
                                                __half2 fx, __half2 fy) {
    const __half2 t = __hfma2(fx, __hsub2(ur, ul), ul);
    const __half2 b = __hfma2(fx, __hsub2(dr, dl), dl);
    return __hfma2(fy, __hsub2(b, t), t);
}

// ---------------------------------------------------------------------------
// Kernel 1: transpose (C, H*W) f32 -> (H*W, C) fp16 (HBM-roofline bound)
// ---------------------------------------------------------------------------
__global__ void transpose_kernel(const float* __restrict__ in) {
    __shared__ float tile[32][33];
    const int p0 = blockIdx.x * 32;
    const int c0 = blockIdx.y * 32;
    const int tx = threadIdx.x;
    const int ty = threadIdx.y;

#pragma unroll
    for (int i = 0; i < 32; i += 8) {
        tile[ty + i][tx] = in[(size_t)(c0 + ty + i) * (HF * WF) + (p0 + tx)];
    }
    __syncthreads();

    const int tid = ty * 32 + tx;
#pragma unroll
    for (int it = 0; it < 2; it++) {
        const int idx = tid + it * 256;
        const int p_local = idx >> 4;
        const int k = idx & 15;
        __half2 h = __floats2half2_rn(tile[2 * k][p_local], tile[2 * k + 1][p_local]);
        *(__half2*)&g_featTh[(size_t)(p0 + p_local) * CH + c0 + 2 * k] = h;
    }
}

// ---------------------------------------------------------------------------
// Kernel 2: ROI align + 2x2 max subsample, xs-major mapping.
// Grid: (N, 7). Block: 224 threads = 14 xs sample-columns x 16 c16 chunks.
// Each thread: one x sample column, 16 channels, both sy rows ->
// 8 corner addresses x 32B = 16 straight-line LDG.128 (front-batchable).
// Vertical max in-thread; horizontal 2x1 max via shfl_xor(16).
// ---------------------------------------------------------------------------
__global__ __launch_bounds__(224) void roialign_kernel(
    const float* __restrict__ rois,
    const float* __restrict__ img_size,
    float* __restrict__ out)
{
    const int n   = blockIdx.x;
    const int ph  = blockIdx.y;
    const int tid = threadIdx.x;
    const int xs  = tid >> 4;    // 0..13
    const int c16 = tid & 15;    // 0..15

    __shared__ __align__(16) __half s_half[WO * SPITCH];  // 3.7 KB

    const float4 roi = __ldg((const float4*)rois + n);
    const float Hi = __ldg(img_size);
    const float Wi = __ldg(img_size + 1);
    const float sy_scale = (HF - 1.0f) / (Hi - 1.0f);
    const float sx_scale = (WF - 1.0f) / (Wi - 1.0f);
    const float r0 = roi.x * sy_scale;
    const float r1 = roi.y * sx_scale;
    const float h_step = (roi.z * sy_scale - r0) * (1.0f / (float)HS);
    const float w_step = (roi.w * sx_scale - r1) * (1.0f / (float)WS);

    // --- geometry: 1 x coord, 2 y coords ---
    const float xx  = ((float)xs + 0.5f) * w_step + r1;
    const float yy0 = ((float)(2 * ph) + 0.5f) * h_step + r0;
    const float yy1 = yy0 + h_step;
    const int ix  = __float2int_rd(xx);
    const int iy0 = __float2int_rd(yy0);
    const int iy1 = __float2int_rd(yy1);
    const __half2 fx  = __float2half2_rn(xx  - (float)ix);
    const __half2 fy0 = __float2half2_rn(yy0 - (float)iy0);
    const __half2 fy1 = __float2half2_rn(yy1 - (float)iy1);

    const unsigned cl  = (unsigned)ix  * COL_BYTES;
    const unsigned ru0 = (unsigned)iy0 * ROW_BYTES;
    const unsigned ru1 = (unsigned)iy1 * ROW_BYTES;

    const char* fb = (const char*)g_featTh + c16 * 32;

    // 8 corner byte offsets (floor+1 trick: down/right = +stride, weight-0 safe)
    const unsigned a0 = ru0 + cl;               // u0l
    const unsigned a1 = a0 + COL_BYTES;         // u0r
    const unsigned a2 = a0 + ROW_BYTES;         // d0l
    const unsigned a3 = a2 + COL_BYTES;         // d0r
    const unsigned a4 = ru1 + cl;               // u1l
    const unsigned a5 = a4 + COL_BYTES;         // u1r
    const unsigned a6 = a4 + ROW_BYTES;         // d1l
    const unsigned a7 = a6 + COL_BYTES;         // d1r

    // --- 16 straight-line 16B loads (lo = ch 0..7 of chunk, hi = ch 8..15) ---
    const uint4 v0a = *(const uint4*)(fb + a0);
    const uint4 v1a = *(const uint4*)(fb + a1);
    const uint4 v2a = *(const uint4*)(fb + a2);
    const uint4 v3a = *(const uint4*)(fb + a3);
    const uint4 v4a = *(const uint4*)(fb + a4);
    const uint4 v5a = *(const uint4*)(fb + a5);
    const uint4 v6a = *(const uint4*)(fb + a6);
    const uint4 v7a = *(const uint4*)(fb + a7);
    const uint4 v0b = *(const uint4*)(fb + a0 + 16);
    const uint4 v1b = *(const uint4*)(fb + a1 + 16);
    const uint4 v2b = *(const uint4*)(fb + a2 + 16);
    const uint4 v3b = *(const uint4*)(fb + a3 + 16);
    const uint4 v4b = *(const uint4*)(fb + a4 + 16);
    const uint4 v5b = *(const uint4*)(fb + a5 + 16);
    const uint4 v6b = *(const uint4*)(fb + a6 + 16);
    const uint4 v7b = *(const uint4*)(fb + a7 + 16);

    unsigned m[8];
    {
        const unsigned* u0 = (const unsigned*)&v0a;
        const unsigned* u1 = (const unsigned*)&v1a;
        const unsigned* u2 = (const unsigned*)&v2a;
        const unsigned* u3 = (const unsigned*)&v3a;
        const unsigned* u4 = (const unsigned*)&v4a;
        const unsigned* u5 = (const unsigned*)&v5a;
        const unsigned* u6 = (const unsigned*)&v6a;
        const unsigned* u7 = (const unsigned*)&v7a;
#pragma unroll
        for (int j = 0; j < 4; j++) {
            const __half2 s0 = lerp2(u2h2(u0[j]), u2h2(u1[j]), u2h2(u2[j]), u2h2(u3[j]), fx, fy0);
            const __half2 s1 = lerp2(u2h2(u4[j]), u2h2(u5[j]), u2h2(u6[j]), u2h2(u7[j]), fx, fy1);
            const __half2 vm = __hmax2(s0, s1);
            m[j] = *(const unsigned*)&vm;
        }
        const unsigned* w0 = (const unsigned*)&v0b;
        const unsigned* w1 = (const unsigned*)&v1b;
        const unsigned* w2 = (const unsigned*)&v2b;
        const unsigned* w3 = (const unsigned*)&v3b;
        const unsigned* w4 = (const unsigned*)&v4b;
        const unsigned* w5 = (const unsigned*)&v5b;
        const unsigned* w6 = (const unsigned*)&v6b;
        const unsigned* w7 = (const unsigned*)&v7b;
#pragma unroll
        for (int j = 0; j < 4; j++) {
            const __half2 s0 = lerp2(u2h2(w0[j]), u2h2(w1[j]), u2h2(w2[j]), u2h2(w3[j]), fx, fy0);
            const __half2 s1 = lerp2(u2h2(w4[j]), u2h2(w5[j]), u2h2(w6[j]), u2h2(w7[j]), fx, fy1);
            const __half2 vm = __hmax2(s0, s1);
            m[4 + j] = *(const unsigned*)&vm;
        }
    }

    // --- horizontal max across xs pairs: partner tid = tid ^ 16 (same warp) ---
#pragma unroll
    for (int j = 0; j < 8; j++) {
        const unsigned p = __shfl_xor_sync(0xffffffffu, m[j], 16);
        const __half2 vm = __hmax2(u2h2(m[j]), u2h2(p));
        m[j] = *(const unsigned*)&vm;
    }

    // even-xs threads stage the final (pw, c16) result: 32B
    if (!(xs & 1)) {
        const int pw = xs >> 1;
        __half* sp = &s_half[pw * SPITCH + c16 * 16];
        *(uint4*)(sp)     = make_uint4(m[0], m[1], m[2], m[3]);
        *(uint4*)(sp + 8) = make_uint4(m[4], m[5], m[6], m[7]);
    }
    __syncthreads();

    // --- writeback: 224 = 32*7 -> fixed pw per thread, c += 32 per iter ---
    {
        int c  = tid / 7;            // 0..31 (magic-mul once)
        const int pw = tid - c * 7;  // fixed
        const __half* sp = s_half + pw * SPITCH;
        float* gp = out + (size_t)n * (CH * HO * WO) + (size_t)c * (HO * WO)
                        + ph * WO + pw;
#pragma unroll
        for (int k = 0; k < 8; k++) {
            *gp = __half2float(sp[c]);
            c  += 32;
            gp += 32 * (HO * WO);
        }
    }
}

extern "C" void kernel_launch(void* const* d_in, const int* in_sizes, int n_in,
                              void* d_out, int out_size) {
    const float* features = (const float*)d_in[0];  // (1, 256, 200, 200)
    const float* rois     = (const float*)d_in[1];  // (512, 4)
    const float* img_size = (const float*)d_in[2];  // (2,)
    float* out = (float*)d_out;                     // (512, 256, 7, 7)

    const int n_rois = in_sizes[1] / 4;

    dim3 tgrid(HF * WF / 32, CH / 32);
    dim3 tblock(32, 8);
    transpose_kernel<<<tgrid, tblock>>>(features);

    dim3 rgrid(n_rois, HO);
    roialign_kernel<<<rgrid, 224>>>(rois, img_size, out);
}

// round 8
// speedup vs baseline: 1.1404x; 1.1404x over previous
#include <cuda_runtime.h>
#include <cuda_fp16.h>
#include <math.h>

#define HF 200
#define WF 200
#define CH 256
#define HO 7
#define WO 7
#define SUBS 2
#define HS (HO * SUBS)   // 14
#define WS (WO * SUBS)   // 14

#define ROW_BYTES (WF * CH * 2)   // 102400
#define COL_BYTES (CH * 2)        // 512
#define SPITCH 264                // halves per staged position (256 + 8 pad)

// Channels-last fp16 scratch copy: g_featTh[(y*WF + x)*CH + c]  (20.5 MB)
__device__ __align__(16) __half g_featTh[HF * WF * CH];

static __device__ __forceinline__ __half2 u2h2(unsigned u) {
    return *reinterpret_cast<__half2*>(&u);
}

// ---------------------------------------------------------------------------
// Kernel 1: transpose (C, H*W) f32 -> (H*W, C) fp16 (HBM-roofline bound)
// ---------------------------------------------------------------------------
__global__ void transpose_kernel(const float* __restrict__ in) {
    __shared__ float tile[32][33];
    const int p0 = blockIdx.x * 32;
    const int c0 = blockIdx.y * 32;
    const int tx = threadIdx.x;
    const int ty = threadIdx.y;

#pragma unroll
    for (int i = 0; i < 32; i += 8) {
        tile[ty + i][tx] = in[(size_t)(c0 + ty + i) * (HF * WF) + (p0 + tx)];
    }
    __syncthreads();

    const int tid = ty * 32 + tx;
#pragma unroll
    for (int it = 0; it < 2; it++) {
        const int idx = tid + it * 256;
        const int p_local = idx >> 4;
        const int k = idx & 15;
        __half2 h = __floats2half2_rn(tile[2 * k][p_local], tile[2 * k + 1][p_local]);
        *(__half2*)&g_featTh[(size_t)(p0 + p_local) * CH + c0 + 2 * k] = h;
    }
}

// ---------------------------------------------------------------------------
// Kernel 2: ROI align + 2x2 max subsample. R5 structure, occupancy-forced.
// Grid: (N, 7). Block: 224 threads = 7 pw x 32 c8, ALL active.
// __launch_bounds__(224, 9): 32-reg cap -> ~98% occupancy (63/64 warps).
// ---------------------------------------------------------------------------
__global__ __launch_bounds__(224, 9) void roialign_kernel(
    const float* __restrict__ rois,
    const float* __restrict__ img_size,
    float* __restrict__ out)
{
    const int n   = blockIdx.x;
    const int ph  = blockIdx.y;
    const int tid = threadIdx.x;
    const int pw  = tid >> 5;     // 0..6
    const int c8  = tid & 31;     // 0..31

    __shared__ __align__(16) __half s_half[WO * SPITCH];  // 3.7 KB

    const float4 roi = __ldg((const float4*)rois + n);
    const float Hi = __ldg(img_size);
    const float Wi = __ldg(img_size + 1);
    const float sy_scale = (HF - 1.0f) / (Hi - 1.0f);
    const float sx_scale = (WF - 1.0f) / (Wi - 1.0f);
    const float r0 = roi.x * sy_scale;
    const float r1 = roi.y * sx_scale;
    const float h_step = (roi.z * sy_scale - r0) * (1.0f / (float)HS);
    const float w_step = (roi.w * sx_scale - r1) * (1.0f / (float)WS);

    // --- per-thread geometry (2 y coords, 2 x coords) ---
    const float yy0 = ((float)(2 * ph) + 0.5f) * h_step + r0;
    const float yy1 = yy0 + h_step;
    const float xx0 = ((float)(2 * pw) + 0.5f) * w_step + r1;
    const float xx1 = xx0 + w_step;

    const int iy0 = __float2int_rd(yy0);
    const int iy1 = __float2int_rd(yy1);
    const int ix0 = __float2int_rd(xx0);
    const int ix1 = __float2int_rd(xx1);

    const __half2 fy0 = __float2half2_rn(yy0 - (float)iy0);
    const __half2 fy1 = __float2half2_rn(yy1 - (float)iy1);
    const __half2 fx0 = __float2half2_rn(xx0 - (float)ix0);
    const __half2 fx1 = __float2half2_rn(xx1 - (float)ix1);

    // row/col byte offsets; "down"/"right" = +1 stride (floor+1, weight-0 safe)
    const unsigned ru0 = (unsigned)iy0 * ROW_BYTES;
    const unsigned ru1 = (unsigned)iy1 * ROW_BYTES;
    const unsigned rd0 = ru0 + ROW_BYTES;
    const unsigned rd1 = ru1 + ROW_BYTES;
    const unsigned cl0 = (unsigned)ix0 * COL_BYTES;
    const unsigned cl1 = (unsigned)ix1 * COL_BYTES;
    const unsigned cr0 = cl0 + COL_BYTES;
    const unsigned cr1 = cl1 + COL_BYTES;

    const char* fb = (const char*)g_featTh + c8 * 16;

    uint4 v[16];
    v[ 0] = *(const uint4*)(fb + (ru0 + cl0));
    v[ 1] = *(const uint4*)(fb + (ru0 + cr0));
    v[ 2] = *(const uint4*)(fb + (rd0 + cl0));
    v[ 3] = *(const uint4*)(fb + (rd0 + cr0));
    v[ 4] = *(const uint4*)(fb + (ru0 + cl1));
    v[ 5] = *(const uint4*)(fb + (ru0 + cr1));
    v[ 6] = *(const uint4*)(fb + (rd0 + cl1));
    v[ 7] = *(const uint4*)(fb + (rd0 + cr1));
    v[ 8] = *(const uint4*)(fb + (ru1 + cl0));
    v[ 9] = *(const uint4*)(fb + (ru1 + cr0));
    v[10] = *(const uint4*)(fb + (rd1 + cl0));
    v[11] = *(const uint4*)(fb + (rd1 + cr0));
    v[12] = *(const uint4*)(fb + (ru1 + cl1));
    v[13] = *(const uint4*)(fb + (ru1 + cr1));
    v[14] = *(const uint4*)(fb + (rd1 + cl1));
    v[15] = *(const uint4*)(fb + (rd1 + cr1));

    __half2 best[4];
    const __half2 ninf = __float2half2_rn(-60000.0f);
#pragma unroll
    for (int j = 0; j < 4; j++) best[j] = ninf;

    const __half2 fxs[4] = {fx0, fx1, fx0, fx1};
    const __half2 fys[4] = {fy0, fy0, fy1, fy1};

#pragma unroll
    for (int s = 0; s < 4; s++) {
        const unsigned* pul = (const unsigned*)&v[s * 4 + 0];
        const unsigned* pur = (const unsigned*)&v[s * 4 + 1];
        const unsigned* pdl = (const unsigned*)&v[s * 4 + 2];
        const unsigned* pdr = (const unsigned*)&v[s * 4 + 3];
        const __half2 fx2 = fxs[s];
        const __half2 fy2 = fys[s];
#pragma unroll
        for (int j = 0; j < 4; j++) {
            const __half2 ul = u2h2(pul[j]);
            const __half2 ur = u2h2(pur[j]);
            const __half2 dl = u2h2(pdl[j]);
            const __half2 dr = u2h2(pdr[j]);
            const __half2 t = __hfma2(fx2, __hsub2(ur, ul), ul);
            const __half2 b = __hfma2(fx2, __hsub2(dr, dl), dl);
            const __half2 vv = __hfma2(fy2, __hsub2(b, t), t);
            best[j] = __hmax2(best[j], vv);
        }
    }

    // stage 8 halves (16B) at (pw, c8)
    *(uint4*)&s_half[pw * SPITCH + c8 * 8] = *(const uint4*)best;
    __syncthreads();

    // --- writeback: 1792 floats = 224 x 8; fixed pw, c += 32 per iter ---
    {
        int c  = tid / 7;            // 0..31 (magic-mul once)
        const int wpw = tid - c * 7; // fixed 0..6
        const __half* sp = s_half + wpw * SPITCH;
        float* gp = out + (size_t)n * (CH * HO * WO) + (size_t)c * (HO * WO)
                        + ph * WO + wpw;
#pragma unroll
        for (int k = 0; k < 8; k++) {
            *gp = __half2float(sp[c]);
            c  += 32;
            gp += 32 * (HO * WO);
        }
    }
}

extern "C" void kernel_launch(void* const* d_in, const int* in_sizes, int n_in,
                              void* d_out, int out_size) {
    const float* features = (const float*)d_in[0];  // (1, 256, 200, 200)
    const float* rois     = (const float*)d_in[1];  // (512, 4)
    const float* img_size = (const float*)d_in[2];  // (2,)
    float* out = (float*)d_out;                     // (512, 256, 7, 7)

    const int n_rois = in_sizes[1] / 4;

    dim3 tgrid(HF * WF / 32, CH / 32);
    dim3 tblock(32, 8);
    transpose_kernel<<<tgrid, tblock>>>(features);

    dim3 rgrid(n_rois, HO);
    roialign_kernel<<<rgrid, 224>>>(rois, img_size, out);
}